// round 16
// baseline (speedup 1.0000x reference)
#include <cuda_runtime.h>
#include <cuda_bf16.h>
#include <math.h>

// ---------------- static problem dims ----------------
// src: (8, 128, 64, 256). Token n = (b*128 + r)*64 + c  = b*8192 + r*64 + c
#define NTOK 65536
#define EDIM 256

// ---------------- scratch (device globals; no allocations) ----------------
__device__ float g_x0 [(size_t)NTOK * 256];
__device__ float g_qkv[(size_t)NTOK * 768];
__device__ float g_att[(size_t)NTOK * 256];
__device__ float g_xn [(size_t)NTOK * 256];
__device__ float g_y  [(size_t)NTOK * 256];
__device__ float g_kv2[(size_t)512 * 96 * 512];
__device__ float g_z  [(size_t)NTOK * 256];
__device__ float g_h  [(size_t)NTOK * 1024];
__device__ float2 g_rope[128 * 16];              // (cos, sin) per (pos, freq)

__constant__ float c_invfreq[16] = {
  1.0f, 0.5623413251903491f, 0.31622776601683794f, 0.17782794100389228f,
  0.1f, 0.05623413251903491f, 0.031622776601683794f, 0.017782794100389228f,
  0.01f, 0.005623413251903491f, 0.0031622776601683794f, 0.0017782794100389229f,
  0.001f, 0.0005623413251903491f, 0.00031622776601683794f, 0.00017782794100389227f
};

enum { MAP_ID = 0, MAP_CTX = 1, MAP_QRY = 2 };
enum { EPI_B = 0, EPI_RES = 1, EPI_GELU = 2 };

template<int MAP>
__device__ __forceinline__ int map_row(int m) {
  if (MAP == MAP_ID) {
    return m;
  } else if (MAP == MAP_CTX) {            // m = b2*96 + r,  r in [0,96)
    int b2 = m / 96, r = m - b2 * 96;
    int b = b2 >> 6, c = b2 & 63;
    return b * 8192 + r * 64 + c;
  } else {                                 // m = b2*32 + i,  r = 96 + i
    int b2 = m >> 5, i = m & 31;
    int b = b2 >> 6, c = b2 & 63;
    return b * 8192 + (96 + i) * 64 + c;
  }
}

__device__ __forceinline__ float tf32r(float x) {
  float y;
  asm("cvt.rna.tf32.f32 %0, %1;" : "=f"(y) : "f"(x));
  return y;
}

__device__ __forceinline__ float sanf(float x) { return isfinite(x) ? x : 0.f; }

__device__ __forceinline__ float gelu_t(float x) {
  float x2 = x * x;
  float tt = x * fmaf(0.035677408136300125f, x2, 0.7978845608028654f);
  float th;
  asm("tanh.approx.f32 %0, %1;" : "=f"(th) : "f"(tt));
  float hx = 0.5f * x;
  return fmaf(hx, th, hx);
}

__device__ __forceinline__ void mma_tf32(float c[4], const unsigned a[4], const unsigned b[2]) {
  asm volatile(
    "mma.sync.aligned.m16n8k8.row.col.f32.tf32.tf32.f32 "
    "{%0,%1,%2,%3}, {%4,%5,%6,%7}, {%8,%9}, {%0,%1,%2,%3};\n"
    : "+f"(c[0]), "+f"(c[1]), "+f"(c[2]), "+f"(c[3])
    : "r"(a[0]), "r"(a[1]), "r"(a[2]), "r"(a[3]), "r"(b[0]), "r"(b[1]));
}

// ---------------- RoPE table init ----------------
__global__ void rope_table_kernel() {
  int i = threadIdx.x + blockIdx.x * blockDim.x;   // 0..2047
  int r = i >> 4, f = i & 15;
  float sn, cs;
  sincosf((float)r * c_invfreq[f], &sn, &cs);
  g_rope[i] = make_float2(cs, sn);
}

// ---------------- TF32 NT GEMM (wide N): C = A.W^T + bias (+gelu) ------------
template<int MAPA, int MAPC, int EPI, int SANA>
__global__ __launch_bounds__(256, 2)
void gemm_tf32(const float* __restrict__ A, const float* __restrict__ W,
               const float* __restrict__ bias, float* __restrict__ C,
               int M, int N, int K)
{
  __shared__ float As[2][128][20];
  __shared__ float Bs[2][128][20];
  const int t  = threadIdx.x;
  const int mt = blockIdx.y * 128;
  const int nt = blockIdx.x * 128;
  const int lm = t >> 2;
  const int lk = (t & 3) << 2;

  const int arow0 = map_row<MAPA>(mt + lm);
  const int arow1 = map_row<MAPA>(mt + lm + 64);
  const float* Ap0 = A + (size_t)arow0 * K + lk;
  const float* Ap1 = A + (size_t)arow1 * K + lk;
  const float* Wp0 = W + (size_t)(nt + lm) * K + lk;
  const float* Wp1 = W + (size_t)(nt + lm + 64) * K + lk;

  const int w = t >> 5, lane = t & 31;
  const int wm = w & 1, wn = w >> 1;
  const int g = lane >> 2, tq = lane & 3;

  float acc[4][4][4];
#pragma unroll
  for (int i = 0; i < 4; i++)
#pragma unroll
    for (int j = 0; j < 4; j++)
#pragma unroll
      for (int r = 0; r < 4; r++) acc[i][j][r] = 0.f;

  float4 sa0 = *(const float4*)Ap0;
  float4 sa1 = *(const float4*)Ap1;
  float4 sb0 = *(const float4*)Wp0;
  float4 sb1 = *(const float4*)Wp1;

  int buf = 0;
  for (int k0 = 0; k0 < K; k0 += 16) {
    if (SANA) {
      sa0.x = sanf(sa0.x); sa0.y = sanf(sa0.y); sa0.z = sanf(sa0.z); sa0.w = sanf(sa0.w);
      sa1.x = sanf(sa1.x); sa1.y = sanf(sa1.y); sa1.z = sanf(sa1.z); sa1.w = sanf(sa1.w);
    }
    *(float4*)&As[buf][lm][lk]      = make_float4(tf32r(sa0.x), tf32r(sa0.y), tf32r(sa0.z), tf32r(sa0.w));
    *(float4*)&As[buf][lm + 64][lk] = make_float4(tf32r(sa1.x), tf32r(sa1.y), tf32r(sa1.z), tf32r(sa1.w));
    *(float4*)&Bs[buf][lm][lk]      = make_float4(tf32r(sb0.x), tf32r(sb0.y), tf32r(sb0.z), tf32r(sb0.w));
    *(float4*)&Bs[buf][lm + 64][lk] = make_float4(tf32r(sb1.x), tf32r(sb1.y), tf32r(sb1.z), tf32r(sb1.w));
    __syncthreads();
    if (k0 + 16 < K) {
      sa0 = *(const float4*)(Ap0 + k0 + 16);
      sa1 = *(const float4*)(Ap1 + k0 + 16);
      sb0 = *(const float4*)(Wp0 + k0 + 16);
      sb1 = *(const float4*)(Wp1 + k0 + 16);
    }
#pragma unroll
    for (int ks = 0; ks < 16; ks += 8) {
      unsigned ar[4][4], br[4][2];
#pragma unroll
      for (int im = 0; im < 4; im++) {
        int m = wm * 64 + im * 16;
        ar[im][0] = __float_as_uint(As[buf][m + g    ][ks + tq    ]);
        ar[im][1] = __float_as_uint(As[buf][m + g + 8][ks + tq    ]);
        ar[im][2] = __float_as_uint(As[buf][m + g    ][ks + tq + 4]);
        ar[im][3] = __float_as_uint(As[buf][m + g + 8][ks + tq + 4]);
      }
#pragma unroll
      for (int jn = 0; jn < 4; jn++) {
        int n = wn * 32 + jn * 8;
        br[jn][0] = __float_as_uint(Bs[buf][n + g][ks + tq    ]);
        br[jn][1] = __float_as_uint(Bs[buf][n + g][ks + tq + 4]);
      }
#pragma unroll
      for (int im = 0; im < 4; im++)
#pragma unroll
        for (int jn = 0; jn < 4; jn++)
          mma_tf32(acc[im][jn], ar[im], br[jn]);
    }
    buf ^= 1;
  }

#pragma unroll
  for (int im = 0; im < 4; im++) {
    int r0 = mt + wm * 64 + im * 16 + g;
    int cr0 = map_row<MAPC>(r0);
    int cr1 = map_row<MAPC>(r0 + 8);
#pragma unroll
    for (int jn = 0; jn < 4; jn++) {
      int n = nt + wn * 32 + jn * 8 + 2 * tq;
      float2 bv = *(const float2*)&bias[n];
      float o0 = acc[im][jn][0] + bv.x, o1 = acc[im][jn][1] + bv.y;
      float o2 = acc[im][jn][2] + bv.x, o3 = acc[im][jn][3] + bv.y;
      if (EPI == EPI_GELU) {
        o0 = gelu_t(o0); o1 = gelu_t(o1); o2 = gelu_t(o2); o3 = gelu_t(o3);
      }
      *(float2*)&C[(size_t)cr0 * N + n] = make_float2(o0, o1);
      *(float2*)&C[(size_t)cr1 * N + n] = make_float2(o2, o3);
    }
  }
}

// -------- TF32 NT GEMM, N=256 fixed, fused bias+residual+LayerNorm -----------
// Tile 64x256, BK=8 double-buffered, 256 threads (2M x 4N warps, 32x64/warp).
// Epilogue: o = acc + bias + res; LN over the full 256-wide row (intra-warp
// shfl over tq group + cross-warp smem reduction); optional pre-LN write.
template<int MAPA, int MAPC, int SANR, int WPRE>
__global__ __launch_bounds__(256, 2)
void gemm_ln(const float* __restrict__ A, const float* __restrict__ W,
             const float* __restrict__ bias, const float* __restrict__ Res,
             const float* __restrict__ lng, const float* __restrict__ lnb,
             float* __restrict__ Cpre, float* __restrict__ Cpost,
             int M, int K)
{
  __shared__ float As[2][64][12];
  __shared__ float Bs[2][256][12];
  __shared__ float rs[64][4], rq[64][4];
  const int t  = threadIdx.x;
  const int mt = blockIdx.x * 64;
  const int w = t >> 5, lane = t & 31;
  const int wm = w & 1, wn = w >> 1;
  const int g = lane >> 2, tq = lane & 3;

  const int a_r = (t < 128) ? (t >> 1) : 0;
  const int a_c = (t & 1) << 2;
  const float* Ap = A + (size_t)map_row<MAPA>(mt + a_r) * K + a_c;
  const float* Wp = W + (size_t)t * K;

  float acc[2][8][4];
#pragma unroll
  for (int i = 0; i < 2; i++)
#pragma unroll
    for (int j = 0; j < 8; j++)
#pragma unroll
      for (int r = 0; r < 4; r++) acc[i][j][r] = 0.f;

  float4 sa, sb0, sb1;
  if (t < 128) sa = *(const float4*)Ap;
  sb0 = *(const float4*)Wp;
  sb1 = *(const float4*)(Wp + 4);

  int buf = 0;
  for (int k0 = 0; k0 < K; k0 += 8) {
    if (t < 128)
      *(float4*)&As[buf][a_r][a_c] = make_float4(tf32r(sa.x), tf32r(sa.y), tf32r(sa.z), tf32r(sa.w));
    *(float4*)&Bs[buf][t][0] = make_float4(tf32r(sb0.x), tf32r(sb0.y), tf32r(sb0.z), tf32r(sb0.w));
    *(float4*)&Bs[buf][t][4] = make_float4(tf32r(sb1.x), tf32r(sb1.y), tf32r(sb1.z), tf32r(sb1.w));
    __syncthreads();
    if (k0 + 8 < K) {
      if (t < 128) sa = *(const float4*)(Ap + k0 + 8);
      sb0 = *(const float4*)(Wp + k0 + 8);
      sb1 = *(const float4*)(Wp + k0 + 12);
    }
    unsigned ar[2][4];
#pragma unroll
    for (int im = 0; im < 2; im++) {
      int m = wm * 32 + im * 16;
      ar[im][0] = __float_as_uint(As[buf][m + g    ][tq    ]);
      ar[im][1] = __float_as_uint(As[buf][m + g + 8][tq    ]);
      ar[im][2] = __float_as_uint(As[buf][m + g    ][tq + 4]);
      ar[im][3] = __float_as_uint(As[buf][m + g + 8][tq + 4]);
    }
#pragma unroll
    for (int jn = 0; jn < 8; jn++) {
      int n0 = wn * 64 + jn * 8;
      unsigned br[2];
      br[0] = __float_as_uint(Bs[buf][n0 + g][tq    ]);
      br[1] = __float_as_uint(Bs[buf][n0 + g][tq + 4]);
      mma_tf32(acc[0][jn], ar[0], br);
      mma_tf32(acc[1][jn], ar[1], br);
    }
    buf ^= 1;
  }

  // ---- epilogue: bias + residual, then fused LayerNorm over N=256 ----
  int crow[2][2];
#pragma unroll
  for (int im = 0; im < 2; im++) {
    crow[im][0] = map_row<MAPC>(mt + wm * 32 + im * 16 + g);
    crow[im][1] = map_row<MAPC>(mt + wm * 32 + im * 16 + g + 8);
  }
  float2 bv[8], gm[8], bt[8];
#pragma unroll
  for (int jn = 0; jn < 8; jn++) {
    int n = wn * 64 + jn * 8 + 2 * tq;
    bv[jn] = *(const float2*)&bias[n];
    gm[jn] = *(const float2*)&lng[n];
    bt[jn] = *(const float2*)&lnb[n];
  }
#pragma unroll
  for (int im = 0; im < 2; im++)
#pragma unroll
    for (int rr = 0; rr < 2; rr++) {
      const float* Rp = Res + (size_t)crow[im][rr] * 256;
#pragma unroll
      for (int jn = 0; jn < 8; jn++) {
        int n = wn * 64 + jn * 8 + 2 * tq;
        float2 v = *(const float2*)&Rp[n];
        if (SANR) { v.x = sanf(v.x); v.y = sanf(v.y); }
        acc[im][jn][rr * 2 + 0] += bv[jn].x + v.x;
        acc[im][jn][rr * 2 + 1] += bv[jn].y + v.y;
      }
    }
  // partial row sums over this warp's 64 columns
#pragma unroll
  for (int im = 0; im < 2; im++)
#pragma unroll
    for (int rr = 0; rr < 2; rr++) {
      float s = 0.f, q = 0.f;
#pragma unroll
      for (int jn = 0; jn < 8; jn++) {
        float o0 = acc[im][jn][rr * 2], o1 = acc[im][jn][rr * 2 + 1];
        s += o0 + o1;
        q = fmaf(o0, o0, q); q = fmaf(o1, o1, q);
      }
      s += __shfl_xor_sync(0xffffffffu, s, 1);
      s += __shfl_xor_sync(0xffffffffu, s, 2);
      q += __shfl_xor_sync(0xffffffffu, q, 1);
      q += __shfl_xor_sync(0xffffffffu, q, 2);
      if (tq == 0) {
        int l = wm * 32 + im * 16 + rr * 8 + g;
        rs[l][wn] = s; rq[l][wn] = q;
      }
    }
  __syncthreads();
#pragma unroll
  for (int im = 0; im < 2; im++)
#pragma unroll
    for (int rr = 0; rr < 2; rr++) {
      int l = wm * 32 + im * 16 + rr * 8 + g;
      float m = (rs[l][0] + rs[l][1] + rs[l][2] + rs[l][3]) * 0.00390625f;
      float vv = (rq[l][0] + rq[l][1] + rq[l][2] + rq[l][3]) * 0.00390625f - m * m;
      float rstd = rsqrtf(vv + 1e-5f);
      size_t rowoff = (size_t)crow[im][rr] * 256;
#pragma unroll
      for (int jn = 0; jn < 8; jn++) {
        int n = wn * 64 + jn * 8 + 2 * tq;
        float o0 = acc[im][jn][rr * 2], o1 = acc[im][jn][rr * 2 + 1];
        if (WPRE) *(float2*)&Cpre[rowoff + n] = make_float2(o0, o1);
        float y0 = (o0 - m) * rstd * gm[jn].x + bt[jn].x;
        float y1 = (o1 - m) * rstd * gm[jn].y + bt[jn].y;
        *(float2*)&Cpost[rowoff + n] = make_float2(y0, y1);
      }
    }
}

// ---------------- stage-1 attention (mma): per (b1, h), L=64, hd=32 ----------
__global__ __launch_bounds__(256)
void att1_kernel(const float* __restrict__ qkv, float* __restrict__ out)
{
  __shared__ float Q[64][36], K[64][36], Vt[32][68], P[64][68];
  const int blk = blockIdx.x;
  const int b1 = blk >> 3, h = blk & 7;
  const int t = threadIdx.x;
  const size_t base = (size_t)b1 * 64 * 768 + h * 32;
  const int w = t >> 5, lane = t & 31;
  const int g = lane >> 2, tq = lane & 3;

#pragma unroll
  for (int i = 0; i < 2; i++) {
    int e = t + i * 256;
    int c = e >> 3, d4 = (e & 7) * 4;
    size_t o = base + (size_t)c * 768 + d4;
    float4 q4 = *(const float4*)(qkv + o);
    float4 k4 = *(const float4*)(qkv + o + 256);
    float4 v4 = *(const float4*)(qkv + o + 512);
    *(float4*)&Q[c][d4] = make_float4(tf32r(q4.x), tf32r(q4.y), tf32r(q4.z), tf32r(q4.w));
    *(float4*)&K[c][d4] = make_float4(tf32r(k4.x), tf32r(k4.y), tf32r(k4.z), tf32r(k4.w));
    Vt[d4 + 0][c] = tf32r(v4.x); Vt[d4 + 1][c] = tf32r(v4.y);
    Vt[d4 + 2][c] = tf32r(v4.z); Vt[d4 + 3][c] = tf32r(v4.w);
  }
  __syncthreads();

  const float scale = 0.17677669529663687f;   // 1/sqrt(32)
  {
    const int wm = w >> 1, wn = w & 1;
    const int m0 = wm * 16;
    float c_[4][4];
#pragma unroll
    for (int jn = 0; jn < 4; jn++)
#pragma unroll
      for (int r = 0; r < 4; r++) c_[jn][r] = 0.f;
#pragma unroll
    for (int ks = 0; ks < 32; ks += 8) {
      unsigned ar[4];
      ar[0] = __float_as_uint(Q[m0 + g    ][ks + tq    ]);
      ar[1] = __float_as_uint(Q[m0 + g + 8][ks + tq    ]);
      ar[2] = __float_as_uint(Q[m0 + g    ][ks + tq + 4]);
      ar[3] = __float_as_uint(Q[m0 + g + 8][ks + tq + 4]);
#pragma unroll
      for (int jn = 0; jn < 4; jn++) {
        int n0 = wn * 32 + jn * 8;
        unsigned br[2];
        br[0] = __float_as_uint(K[n0 + g][ks + tq    ]);
        br[1] = __float_as_uint(K[n0 + g][ks + tq + 4]);
        mma_tf32(c_[jn], ar, br);
      }
    }
#pragma unroll
    for (int jn = 0; jn < 4; jn++) {
      int col = wn * 32 + jn * 8 + 2 * tq;
      *(float2*)&P[m0 + g    ][col] = make_float2(c_[jn][0] * scale, c_[jn][1] * scale);
      *(float2*)&P[m0 + g + 8][col] = make_float2(c_[jn][2] * scale, c_[jn][3] * scale);
    }
  }
  __syncthreads();

#pragma unroll
  for (int rr = 0; rr < 8; rr++) {
    int r = w * 8 + rr;
    float a = P[r][lane], b = P[r][lane + 32];
    float mx = fmaxf(a, b);
#pragma unroll
    for (int o = 16; o > 0; o >>= 1) mx = fmaxf(mx, __shfl_xor_sync(0xffffffffu, mx, o));
    float ea = __expf(a - mx), eb = __expf(b - mx);
    float sm = ea + eb;
#pragma unroll
    for (int o = 16; o > 0; o >>= 1) sm += __shfl_xor_sync(0xffffffffu, sm, o);
    float inv = 1.f / sm;
    P[r][lane] = tf32r(ea * inv); P[r][lane + 32] = tf32r(eb * inv);
  }
  __syncthreads();

  {
    const int wm = w >> 1, wn = w & 1;
    const int m0 = wm * 16;
    float o_[2][4];
#pragma unroll
    for (int jn = 0; jn < 2; jn++)
#pragma unroll
      for (int r = 0; r < 4; r++) o_[jn][r] = 0.f;
#pragma unroll
    for (int ks = 0; ks < 64; ks += 8) {
      unsigned ar[4];
      ar[0] = __float_as_uint(P[m0 + g    ][ks + tq    ]);
      ar[1] = __float_as_uint(P[m0 + g + 8][ks + tq    ]);
      ar[2] = __float_as_uint(P[m0 + g    ][ks + tq + 4]);
      ar[3] = __float_as_uint(P[m0 + g + 8][ks + tq + 4]);
#pragma unroll
      for (int jn = 0; jn < 2; jn++) {
        int n0 = wn * 16 + jn * 8;
        unsigned br[2];
        br[0] = __float_as_uint(Vt[n0 + g][ks + tq    ]);
        br[1] = __float_as_uint(Vt[n0 + g][ks + tq + 4]);
        mma_tf32(o_[jn], ar, br);
      }
    }
    int row0 = b1 * 64 + m0 + g;
#pragma unroll
    for (int jn = 0; jn < 2; jn++) {
      int col = h * 32 + wn * 16 + jn * 8 + 2 * tq;
      *(float2*)&out[(size_t)row0 * 256 + col]       = make_float2(o_[jn][0], o_[jn][1]);
      *(float2*)&out[(size_t)(row0 + 8) * 256 + col] = make_float2(o_[jn][2], o_[jn][3]);
    }
  }
}

// ---------------- stage-2 ctx attention (mma): per (b2,h,half): 48 q, 96 keys ----
__global__ __launch_bounds__(256)
void att2_ctx_kernel(const float* __restrict__ qkv, const int* __restrict__ mask,
                     float* __restrict__ out)
{
  __shared__ float Q[48][36], K[96][36], P[48][100];
  __shared__ float kbias[96];
  float* VT = &K[0][0];                 // Vt[d][j] = VT[d*100 + j]; 3200 <= 3456
  const int blk = blockIdx.x;
  const int half = blk & 1, h = (blk >> 1) & 7, b2 = blk >> 4;
  const int b = b2 >> 6, c = b2 & 63;
  const int t = threadIdx.x;
  const int q0 = half * 48;
  const size_t tokbase = (size_t)b * 8192 + c;
  const int w = t >> 5, lane = t & 31;
  const int g = lane >> 2, tq = lane & 3;

  for (int e = t; e < 384; e += 256) {        // Q: 48x32 (raw; rounded post-RoPE)
    int iq = e >> 3, d4 = (e & 7) * 4;
    *(float4*)&Q[iq][d4] = *(const float4*)(qkv + (tokbase + (size_t)(q0 + iq) * 64) * 768 + h * 32 + d4);
  }
#pragma unroll
  for (int i = 0; i < 3; i++) {               // K: 96x32
    int e = t + i * 256;
    int r = e >> 3, d4 = (e & 7) * 4;
    *(float4*)&K[r][d4] = *(const float4*)(qkv + (tokbase + (size_t)r * 64) * 768 + 256 + h * 32 + d4);
  }
  if (t < 96) kbias[t] = (mask[b * 128 + t] > 0) ? 0.f : -1e9f;
  __syncthreads();
  for (int e = t; e < 96 * 16; e += 256) {    // RoPE K (pos r) via table + round
    int r = e >> 4, i = e & 15;
    float2 t2 = __ldg(&g_rope[e]);            // e == r*16 + i
    float ev = K[r][2*i], ov = K[r][2*i+1];
    K[r][2*i] = tf32r(ev * t2.x - ov * t2.y); K[r][2*i+1] = tf32r(ev * t2.y + ov * t2.x);
  }
  for (int e = t; e < 48 * 16; e += 256) {    // RoPE Q (pos q0+iq) via table + round
    int iq = e >> 4, i = e & 15;
    float2 t2 = __ldg(&g_rope[e + q0 * 16]);
    float ev = Q[iq][2*i], ov = Q[iq][2*i+1];
    Q[iq][2*i] = tf32r(ev * t2.x - ov * t2.y); Q[iq][2*i+1] = tf32r(ev * t2.y + ov * t2.x);
  }
  __syncthreads();

  const float scale = 0.17677669529663687f;
  if (w < 6) {                                // scores 48x96: wm 0..2, wn 0..1
    const int wm = w >> 1, wn = w & 1;
    const int m0 = wm * 16;
    float c_[6][4];
#pragma unroll
    for (int jn = 0; jn < 6; jn++)
#pragma unroll
      for (int r = 0; r < 4; r++) c_[jn][r] = 0.f;
#pragma unroll
    for (int ks = 0; ks < 32; ks += 8) {
      unsigned ar[4];
      ar[0] = __float_as_uint(Q[m0 + g    ][ks + tq    ]);
      ar[1] = __float_as_uint(Q[m0 + g + 8][ks + tq    ]);
      ar[2] = __float_as_uint(Q[m0 + g    ][ks + tq + 4]);
      ar[3] = __float_as_uint(Q[m0 + g + 8][ks + tq + 4]);
#pragma unroll
      for (int jn = 0; jn < 6; jn++) {
        int n0 = wn * 48 + jn * 8;
        unsigned br[2];
        br[0] = __float_as_uint(K[n0 + g][ks + tq    ]);
        br[1] = __float_as_uint(K[n0 + g][ks + tq + 4]);
        mma_tf32(c_[jn], ar, br);
      }
    }
#pragma unroll
    for (int jn = 0; jn < 6; jn++) {
      int col = wn * 48 + jn * 8 + 2 * tq;
      float kb0 = kbias[col], kb1 = kbias[col + 1];
      *(float2*)&P[m0 + g    ][col] = make_float2(c_[jn][0] * scale + kb0, c_[jn][1] * scale + kb1);
      *(float2*)&P[m0 + g + 8][col] = make_float2(c_[jn][2] * scale + kb0, c_[jn][3] * scale + kb1);
    }
  }
  __syncthreads();

#pragma unroll
  for (int i = 0; i < 3; i++) {               // V -> Vt (aliases K)
    int e = t + i * 256;
    int r = e >> 3, d4 = (e & 7) * 4;
    float4 v4 = *(const float4*)(qkv + (tokbase + (size_t)r * 64) * 768 + 512 + h * 32 + d4);
    VT[(d4 + 0) * 100 + r] = tf32r(v4.x); VT[(d4 + 1) * 100 + r] = tf32r(v4.y);
    VT[(d4 + 2) * 100 + r] = tf32r(v4.z); VT[(d4 + 3) * 100 + r] = tf32r(v4.w);
  }
#pragma unroll
  for (int rr = 0; rr < 6; rr++) {            // softmax 48 rows / 8 warps
    int r = w * 6 + rr;
    float x0 = P[r][lane], x1 = P[r][lane + 32], x2 = P[r][lane + 64];
    float mx = fmaxf(x0, fmaxf(x1, x2));
#pragma unroll
    for (int o = 16; o > 0; o >>= 1) mx = fmaxf(mx, __shfl_xor_sync(0xffffffffu, mx, o));
    float e0 = __expf(x0 - mx), e1 = __expf(x1 - mx), e2 = __expf(x2 - mx);
    float sm = e0 + e1 + e2;
#pragma unroll
    for (int o = 16; o > 0; o >>= 1) sm += __shfl_xor_sync(0xffffffffu, sm, o);
    float inv = 1.f / sm;
    P[r][lane] = tf32r(e0 * inv); P[r][lane + 32] = tf32r(e1 * inv); P[r][lane + 64] = tf32r(e2 * inv);
  }
  __syncthreads();

  if (w < 6) {                                // AV: P(48x96) x Vt(32x96)
    const int wm = w >> 1, wn = w & 1;
    const int m0 = wm * 16;
    float o_[2][4];
#pragma unroll
    for (int jn = 0; jn < 2; jn++)
#pragma unroll
      for (int r = 0; r < 4; r++) o_[jn][r] = 0.f;
#pragma unroll
    for (int ks = 0; ks < 96; ks += 8) {
      unsigned ar[4];
      ar[0] = __float_as_uint(P[m0 + g    ][ks + tq    ]);
      ar[1] = __float_as_uint(P[m0 + g + 8][ks + tq    ]);
      ar[2] = __float_as_uint(P[m0 + g    ][ks + tq + 4]);
      ar[3] = __float_as_uint(P[m0 + g + 8][ks + tq + 4]);
#pragma unroll
      for (int jn = 0; jn < 2; jn++) {
        int n0 = wn * 16 + jn * 8;
        unsigned br[2];
        br[0] = __float_as_uint(VT[(n0 + g) * 100 + ks + tq    ]);
        br[1] = __float_as_uint(VT[(n0 + g) * 100 + ks + tq + 4]);
        mma_tf32(o_[jn], ar, br);
      }
    }
    size_t row0 = tokbase + (size_t)(q0 + m0 + g) * 64;
    size_t row1 = tokbase + (size_t)(q0 + m0 + g + 8) * 64;
#pragma unroll
    for (int jn = 0; jn < 2; jn++) {
      int col = h * 32 + wn * 16 + jn * 8 + 2 * tq;
      *(float2*)&out[row0 * 256 + col] = make_float2(o_[jn][0], o_[jn][1]);
      *(float2*)&out[row1 * 256 + col] = make_float2(o_[jn][2], o_[jn][3]);
    }
  }
}

// ---------------- stage-2 qry attention (mma): per (b2, h): 32 q, 96 keys -------
__global__ __launch_bounds__(256)
void att2_qry_kernel(const float* __restrict__ qkv, const float* __restrict__ kv2,
                     const int* __restrict__ mask, float* __restrict__ out)
{
  __shared__ float Q[32][36], K[96][36], P[32][100];
  __shared__ float kbias[96];
  float* VT = &K[0][0];                 // Vt[d][j] = VT[d*100 + j]
  const int blk = blockIdx.x;
  const int h = blk & 7, b2 = blk >> 3;
  const int b = b2 >> 6, c = b2 & 63;
  const int t = threadIdx.x;
  const size_t tokbase = (size_t)b * 8192 + c;
  const size_t kvbase = (size_t)b2 * 96 * 512 + h * 32;
  const int w = t >> 5, lane = t & 31;
  const int g = lane >> 2, tq = lane & 3;

  {                                           // Q: 32x32 (one f4 per thread)
    int iq = t >> 3, d4 = (t & 7) * 4;
    *(float4*)&Q[iq][d4] = *(const float4*)(qkv + (tokbase + (size_t)(96 + iq) * 64) * 768 + h * 32 + d4);
  }
#pragma unroll
  for (int i = 0; i < 3; i++) {               // K2: 96x32
    int e = t + i * 256;
    int r = e >> 3, d4 = (e & 7) * 4;
    *(float4*)&K[r][d4] = *(const float4*)(kv2 + kvbase + (size_t)r * 512 + d4);
  }
  if (t < 96) kbias[t] = (mask[b * 128 + t] > 0) ? 0.f : -1e9f;
  __syncthreads();
  for (int e = t; e < 96 * 16; e += 256) {    // RoPE K (pos r) via table + round
    int r = e >> 4, i = e & 15;
    float2 t2 = __ldg(&g_rope[e]);
    float ev = K[r][2*i], ov = K[r][2*i+1];
    K[r][2*i] = tf32r(ev * t2.x - ov * t2.y); K[r][2*i+1] = tf32r(ev * t2.y + ov * t2.x);
  }
  for (int e = t; e < 32 * 16; e += 256) {    // RoPE Q (pos 96+iq) via table + round
    int iq = e >> 4, i = e & 15;
    float2 t2 = __ldg(&g_rope[e + 96 * 16]);
    float ev = Q[iq][2*i], ov = Q[iq][2*i+1];
    Q[iq][2*i] = tf32r(ev * t2.x - ov * t2.y); Q[iq][2*i+1] = tf32r(ev * t2.y + ov * t2.x);
  }
  __syncthreads();

  const float scale = 0.17677669529663687f;
  {                                           // scores 32x96: wm = w&1, wn = w>>1
    const int wm = w & 1, wn = w >> 1;
    const int m0 = wm * 16;
    float c_[3][4];
#pragma unroll
    for (int jn = 0; jn < 3; jn++)
#pragma unroll
      for (int r = 0; r < 4; r++) c_[jn][r] = 0.f;
#pragma unroll
    for (int ks = 0; ks < 32; ks += 8) {
      unsigned ar[4];
      ar[0] = __float_as_uint(Q[m0 + g    ][ks + tq    ]);
      ar[1] = __float_as_uint(Q[m0 + g + 8][ks + tq    ]);
      ar[2] = __float_as_uint(Q[m0 + g    ][ks + tq + 4]);
      ar[3] = __float_as_uint(Q[m0 + g + 8][ks + tq + 4]);
#pragma unroll
      for (int jn = 0; jn < 3; jn++) {
        int n0 = wn * 24 + jn * 8;
        unsigned br[2];
        br[0] = __float_as_uint(K[n0 + g][ks + tq    ]);
        br[1] = __float_as_uint(K[n0 + g][ks + tq + 4]);
        mma_tf32(c_[jn], ar, br);
      }
    }
#pragma unroll
    for (int jn = 0; jn < 3; jn++) {
      int col = wn * 24 + jn * 8 + 2 * tq;
      float kb0 = kbias[col], kb1 = kbias[col + 1];
      *(float2*)&P[m0 + g    ][col] = make_float2(c_[jn][0] * scale + kb0, c_[jn][1] * scale + kb1);
      *(float2*)&P[m0 + g + 8][col] = make_float2(c_[jn][2] * scale + kb0, c_[jn][3] * scale + kb1);
    }
  }
  __syncthreads();

#pragma unroll
  for (int i = 0; i < 3; i++) {               // V2 -> Vt (aliases K)
    int e = t + i * 256;
    int r = e >> 3, d4 = (e & 7) * 4;
    float4 v4 = *(const float4*)(kv2 + kvbase + (size_t)r * 512 + 256 + d4);
    VT[(d4 + 0) * 100 + r] = tf32r(v4.x); VT[(d4 + 1) * 100 + r] = tf32r(v4.y);
    VT[(d4 + 2) * 100 + r] = tf32r(v4.z); VT[(d4 + 3) * 100 + r] = tf32r(v4.w);
  }
#pragma unroll
  for (int rr = 0; rr < 4; rr++) {            // softmax 32 rows / 8 warps
    int r = w * 4 + rr;
    float x0 = P[r][lane], x1 = P[r][lane + 32], x2 = P[r][lane + 64];
    float mx = fmaxf(x0, fmaxf(x1, x2));
#pragma unroll
    for (int o = 16; o > 0; o >>= 1) mx = fmaxf(mx, __shfl_xor_sync(0xffffffffu, mx, o));
    float e0 = __expf(x0 - mx), e1 = __expf(x1 - mx), e2 = __expf(x2 - mx);
    float sm = e0 + e1 + e2;
#pragma unroll
    for (int o = 16; o > 0; o >>= 1) sm += __shfl_xor_sync(0xffffffffu, sm, o);
    float inv = 1.f / sm;
    P[r][lane] = tf32r(e0 * inv); P[r][lane + 32] = tf32r(e1 * inv); P[r][lane + 64] = tf32r(e2 * inv);
  }
  __syncthreads();

  {                                           // AV: P(32x96) x Vt(32x96)
    const int wm = w & 1, wn = w >> 1;
    const int m0 = wm * 16;
    const int n0 = wn * 8;
    float o_[4];
#pragma unroll
    for (int r = 0; r < 4; r++) o_[r] = 0.f;
#pragma unroll
    for (int ks = 0; ks < 96; ks += 8) {
      unsigned ar[4], br[2];
      ar[0] = __float_as_uint(P[m0 + g    ][ks + tq    ]);
      ar[1] = __float_as_uint(P[m0 + g + 8][ks + tq    ]);
      ar[2] = __float_as_uint(P[m0 + g    ][ks + tq + 4]);
      ar[3] = __float_as_uint(P[m0 + g + 8][ks + tq + 4]);
      br[0] = __float_as_uint(VT[(n0 + g) * 100 + ks + tq    ]);
      br[1] = __float_as_uint(VT[(n0 + g) * 100 + ks + tq + 4]);
      mma_tf32(o_, ar, br);
    }
    size_t row0 = tokbase + (size_t)(96 + m0 + g) * 64;
    size_t row1 = tokbase + (size_t)(96 + m0 + g + 8) * 64;
    int col = h * 32 + n0 + 2 * tq;
    *(float2*)&out[row0 * 256 + col] = make_float2(o_[0], o_[1]);
    *(float2*)&out[row1 * 256 + col] = make_float2(o_[2], o_[3]);
  }
}

// ---------------- launch ----------------
extern "C" void kernel_launch(void* const* d_in, const int* in_sizes, int n_in,
                              void* d_out, int out_size)
{
  const float* src  = (const float*)d_in[0];
  const int*   mask = (const int*)d_in[1];
  int base = (in_sizes[2] == 1) ? 3 : 2;
  const float* y_in_w  = (const float*)d_in[base + 0];
  const float* y_in_b  = (const float*)d_in[base + 1];
  const float* y_out_w = (const float*)d_in[base + 2];
  const float* y_out_b = (const float*)d_in[base + 3];
  const float* x_in_w  = (const float*)d_in[base + 4];
  const float* x_in_b  = (const float*)d_in[base + 5];
  const float* x_out_w = (const float*)d_in[base + 6];
  const float* x_out_b = (const float*)d_in[base + 7];
  const float* w1  = (const float*)d_in[base + 8];
  const float* b1  = (const float*)d_in[base + 9];
  const float* w2  = (const float*)d_in[base + 10];
  const float* b2  = (const float*)d_in[base + 11];
  const float* n1g = (const float*)d_in[base + 12];
  const float* n1b = (const float*)d_in[base + 13];
  const float* n2g = (const float*)d_in[base + 14];
  const float* n2b = (const float*)d_in[base + 15];
  const float* n3g = (const float*)d_in[base + 16];
  const float* n3b = (const float*)d_in[base + 17];
  float* out = (float*)d_out;

  float *x0, *qkvb, *attb, *xnb, *yb, *kv2b, *zb, *hb;
  cudaGetSymbolAddress((void**)&x0,   g_x0);
  cudaGetSymbolAddress((void**)&qkvb, g_qkv);
  cudaGetSymbolAddress((void**)&attb, g_att);
  cudaGetSymbolAddress((void**)&xnb,  g_xn);
  cudaGetSymbolAddress((void**)&yb,   g_y);
  cudaGetSymbolAddress((void**)&kv2b, g_kv2);
  cudaGetSymbolAddress((void**)&zb,   g_z);
  cudaGetSymbolAddress((void**)&hb,   g_h);

  rope_table_kernel<<<8, 256>>>();

  // Stage 1: qkv (nan_to_num fused) -> attention -> out-proj + residual + LN1 fused
  gemm_tf32<MAP_ID, MAP_ID, EPI_B, 1><<<dim3(6, 512), 256>>>(src, y_in_w, y_in_b, qkvb, 65536, 768, 256);
  att1_kernel<<<8192, 256>>>(qkvb, attb);
  gemm_ln<MAP_ID, MAP_ID, 1, 0><<<1024, 256>>>(attb, y_out_w, y_out_b, src, n1g, n1b, nullptr, xnb, 65536, 256);

  // Stage 2: column-axis attention with RoPE + key-padding mask
  gemm_tf32<MAP_ID, MAP_ID, EPI_B, 0><<<dim3(6, 512), 256>>>(xnb, x_in_w, x_in_b, qkvb, 65536, 768, 256);
  att2_ctx_kernel<<<8192, 256>>>(qkvb, mask, attb);
  // ctx out-proj + residual; writes pre-LN2 (yb, for kv2 reprojection) and post-LN2 (zb)
  gemm_ln<MAP_CTX, MAP_CTX, 0, 1><<<768, 256>>>(attb, x_out_w, x_out_b, xnb, n2g, n2b, yb, zb, 49152, 256);
  gemm_tf32<MAP_CTX, MAP_ID, EPI_B, 0><<<dim3(4, 384), 256>>>(yb, x_in_w + 256 * 256, x_in_b + 256, kv2b, 49152, 512, 256);
  att2_qry_kernel<<<4096, 256>>>(qkvb, kv2b, mask, attb);
  gemm_ln<MAP_QRY, MAP_QRY, 0, 0><<<256, 256>>>(attb, x_out_w, x_out_b, xnb, n2g, n2b, nullptr, zb, 16384, 256);

  // MLP: gelu GEMM, then out-proj + residual + LN3 fused, direct to d_out
  gemm_tf32<MAP_ID, MAP_ID, EPI_GELU, 0><<<dim3(8, 512), 256>>>(zb, w1, b1, hb, 65536, 1024, 256);
  gemm_ln<MAP_ID, MAP_ID, 0, 0><<<1024, 256>>>(hb, w2, b2, zb, n3g, n3b, nullptr, out, 65536, 1024);
}